// round 7
// baseline (speedup 1.0000x reference)
#include <cuda_runtime.h>
#include <cuda_bf16.h>
#include <cstdint>

// Shapes (fixed by the problem)
#define BSZ    2
#define NN     384
#define DATOM  512
#define DPAIR  128
#define DHID   32
#define NROWS  (BSZ*NN)          // 768

// Scratch (no cudaMalloc allowed)
__device__ float g_ab[NROWS * 64];            // [a | bv]; bv half k-permuted + tf32
__device__ float g_t [NROWS * DPAIR * DHID];  // t[row][p][y'] tf32 bits, k-permuted
__device__ float g_part[4 * NROWS * 64];      // stage1 split-k partials

// k-pair interleave within each 8-group: y -> (y&24) | ((y&3)<<1) | ((y>>2)&1)
__device__ __forceinline__ int kperm(int y) {
    return (y & 24) | ((y & 3) << 1) | ((y >> 2) & 1);
}
// logical B-col l -> physical p within 32-block: q = 8*tg + 2*nt + e
__device__ __forceinline__ int qperm(int l) {
    return ((l & 7) >> 1) * 8 + (l >> 3) * 2 + (l & 1);
}

// ---------------- f32x2 packed-FMA helpers (sm_103a) ----------------
__device__ __forceinline__ unsigned long long pack2(float x, float y) {
    unsigned long long r;
    asm("mov.b64 %0,{%1,%2};" : "=l"(r) : "f"(x), "f"(y));
    return r;
}
__device__ __forceinline__ void unpack2(unsigned long long v, float& x, float& y) {
    asm("mov.b64 {%0,%1},%2;" : "=f"(x), "=f"(y) : "l"(v));
}
__device__ __forceinline__ void fma2(unsigned long long& d,
                                     unsigned long long a,
                                     unsigned long long b) {
    asm("fma.rn.f32x2 %0,%1,%2,%0;" : "+l"(d) : "l"(a), "l"(b));
}

// ---------------- tf32 / async helpers ----------------
__device__ __forceinline__ uint32_t f2tf32(float f) {
    uint32_t u;
    asm("cvt.rna.tf32.f32 %0, %1;" : "=r"(u) : "f"(f));
    return u;
}
__device__ __forceinline__ void mma_tf32(float c[4], const uint32_t a[4],
                                         const uint32_t b[2]) {
    asm("mma.sync.aligned.m16n8k8.row.col.f32.tf32.tf32.f32 "
        "{%0,%1,%2,%3}, {%4,%5,%6,%7}, {%8,%9}, {%0,%1,%2,%3};"
        : "+f"(c[0]), "+f"(c[1]), "+f"(c[2]), "+f"(c[3])
        : "r"(a[0]), "r"(a[1]), "r"(a[2]), "r"(a[3]), "r"(b[0]), "r"(b[1]));
}
__device__ __forceinline__ uint32_t smem_u32(const void* p) {
    uint32_t a;
    asm("{ .reg .u64 t; cvta.to.shared.u64 t, %1; cvt.u32.u64 %0, t; }" : "=r"(a) : "l"(p));
    return a;
}
#define CP_ASYNC16(dst, src) \
    asm volatile("cp.async.ca.shared.global [%0], [%1], 16;" :: "r"(dst), "l"(src))
#define CP_COMMIT() asm volatile("cp.async.commit_group;")
#define CP_WAIT0()  asm volatile("cp.async.wait_group 0;")

// ---------------- Stage 1a: split-k partial GEMM ----------------
__global__ __launch_bounds__(256) void stage1a(
    const float* __restrict__ m, const float* __restrict__ W_in)
{
    __shared__ __align__(16) float m_s[8 * 128];
    __shared__ __align__(16) float w_s[64 * 132];
    int tid = threadIdx.x;
    int rbase = blockIdx.x * 8;
    int kc = blockIdx.y * 128;

    {
        int r = tid >> 5, c = (tid & 31) * 4;
        *(float4*)&m_s[r * 128 + c] =
            *(const float4*)(m + (size_t)(rbase + r) * 512 + kc + c);
    }
#pragma unroll
    for (int k = 0; k < 8; k++) {
        int idx4 = tid + k * 256;
        int h = idx4 >> 5, c = (idx4 & 31) * 4;
        *(float4*)&w_s[h * 132 + c] =
            *(const float4*)(W_in + (size_t)h * 512 + kc + c);
    }
    __syncthreads();

    int h = tid & 63, rg = tid >> 6;
    float acc0 = 0.f, acc1 = 0.f;
#pragma unroll
    for (int x = 0; x < 32; x++) {
        float4 wv = *(const float4*)&w_s[h * 132 + x * 4];
        float4 m0 = *(const float4*)&m_s[rg * 128 + x * 4];
        float4 m1 = *(const float4*)&m_s[(rg + 4) * 128 + x * 4];
        acc0 = fmaf(wv.x, m0.x, acc0); acc0 = fmaf(wv.y, m0.y, acc0);
        acc0 = fmaf(wv.z, m0.z, acc0); acc0 = fmaf(wv.w, m0.w, acc0);
        acc1 = fmaf(wv.x, m1.x, acc1); acc1 = fmaf(wv.y, m1.y, acc1);
        acc1 = fmaf(wv.z, m1.z, acc1); acc1 = fmaf(wv.w, m1.w, acc1);
    }
    float* dst = g_part + (size_t)blockIdx.y * (NROWS * 64);
    dst[(size_t)(rbase + rg) * 64 + h] = acc0;
    dst[(size_t)(rbase + rg + 4) * 64 + h] = acc1;
}

// ---------------- Stage 1b: reduce + bias + mask; bv half k-permuted + tf32 ----------------
__global__ __launch_bounds__(256) void stage1b(
    const float* __restrict__ b_in, const float* __restrict__ op_mask)
{
    int e = blockIdx.x * 256 + threadIdx.x;   // 49152 total
    float s = g_part[e] + g_part[e + NROWS * 64]
            + g_part[e + 2 * NROWS * 64] + g_part[e + 3 * NROWS * 64];
    int row = e >> 6, h = e & 63;
    float val = (s + b_in[h]) * op_mask[row];
    if (h < 32) {
        g_ab[e] = val;                                   // a half: raw fp32
    } else {
        int yp = kperm(h - 32);                          // bv half: permuted + tf32
        g_ab[(size_t)row * 64 + 32 + yp] = __uint_as_float(f2tf32(val));
    }
}

// ---------------- Stage 2: t[row,p,y'] = tf32(sum_x a[row,x]*Wo[p,x,y]), k-permuted ----------------
__global__ __launch_bounds__(256) void stage2_t(const float* __restrict__ W_out)
{
    __shared__ __align__(16) float w_s[16 * 1024];
    __shared__ __align__(16) float a_s[32 * 32];
    int tid = threadIdx.x;
    int pbase = blockIdx.x * 16;
    int rbase = blockIdx.y * 32;

    const float4* wsrc = (const float4*)(W_out + (size_t)pbase * 1024);
    float4* wdst = (float4*)w_s;
#pragma unroll
    for (int k = 0; k < 16; k++) wdst[tid + k * 256] = wsrc[tid + k * 256];
    {
        int r = tid >> 3, c = tid & 7;
        *(float4*)&a_s[r * 32 + c * 4] =
            *(const float4*)(g_ab + (size_t)(rbase + r) * 64 + c * 4);
    }
    __syncthreads();

    int y = tid & 31, q = tid >> 5;
    int yp = kperm(y);
    unsigned long long w2a[16], w2b[16];
#pragma unroll
    for (int x2 = 0; x2 < 16; x2++) {
        w2a[x2] = pack2(w_s[q * 1024 + (2 * x2 + 0) * 32 + y],
                        w_s[q * 1024 + (2 * x2 + 1) * 32 + y]);
        w2b[x2] = pack2(w_s[(q + 8) * 1024 + (2 * x2 + 0) * 32 + y],
                        w_s[(q + 8) * 1024 + (2 * x2 + 1) * 32 + y]);
    }
    float* dst0 = g_t + (size_t)rbase * 4096 + (size_t)(pbase + q) * 32 + yp;
    float* dst1 = g_t + (size_t)rbase * 4096 + (size_t)(pbase + q + 8) * 32 + yp;
#pragma unroll 2
    for (int r = 0; r < 32; r++) {
        unsigned long long acc0 = 0ull, acc1 = 0ull;
#pragma unroll
        for (int xc = 0; xc < 8; xc++) {
            ulonglong2 a2 = *(const ulonglong2*)&a_s[r * 32 + xc * 4];
            fma2(acc0, a2.x, w2a[2 * xc + 0]);
            fma2(acc0, a2.y, w2a[2 * xc + 1]);
            fma2(acc1, a2.x, w2b[2 * xc + 0]);
            fma2(acc1, a2.y, w2b[2 * xc + 1]);
        }
        float lo0, hi0, lo1, hi1;
        unpack2(acc0, lo0, hi0); unpack2(acc1, lo1, hi1);
        dst0[(size_t)r * 4096] = __uint_as_float(f2tf32(lo0 + hi0));
        dst1[(size_t)r * 4096] = __uint_as_float(f2tf32(lo1 + hi1));
    }
}

// ---------------- Stage 3 (warp MMA, tf32, cp.async, permuted layouts) ----------------
// grid (2, NN, BSZ): each CTA = 3 j-chunks of 64 for one (b,i).
// Warp grid 2(j) x 4(p); warp tile 32j x 32p. Pad 40 -> all LDS.64 conflict-free.
// B columns p-permuted so each thread owns 8 contiguous p -> STG.128 epilogue.
#define S3PAD 40
__global__ __launch_bounds__(256, 3) void stage3_mma(
    const float* __restrict__ b_out, const float* __restrict__ op_norm,
    float* __restrict__ out)
{
    __shared__ __align__(16) uint32_t t_s[128 * S3PAD];     // 20.5 KB tf32 bits
    __shared__ __align__(16) uint32_t a_s[2][64 * S3PAD];   // 2 x 10.25 KB tf32 bits
    __shared__ float bo_s[128];

    int tid = threadIdx.x;
    int half = blockIdx.x;        // 0/1: j-chunks 0..2 / 3..5
    int i = blockIdx.y;
    int b = blockIdx.z;
    int row = b * NN + i;

    uint32_t t_base = smem_u32(t_s);
    uint32_t a_base = smem_u32(a_s);

    // async fill t_s with p-permuted rows: t_s row L <- t row (L&~31)|qperm(L&31)
    const float* tsrc = g_t + (size_t)row * 4096;
#pragma unroll
    for (int k = 0; k < 4; k++) {
        int seg = tid + k * 256;                 // 1024 x 16B segments
        int L = seg >> 3, c4 = (seg & 7) * 4;
        int psrc = (L & ~31) | qperm(L & 31);
        CP_ASYNC16(t_base + (uint32_t)(L * S3PAD + c4) * 4, tsrc + psrc * 32 + c4);
    }
    // async fill a_s buf0: bv rows (already tf32 + k-permuted in g_ab)
    const float* absrc = g_ab + (size_t)(b * NN) * 64;
    int jb0 = half * 192;
#pragma unroll
    for (int k = 0; k < 2; k++) {
        int seg = tid + k * 256;
        int j = seg >> 3, c4 = (seg & 7) * 4;
        CP_ASYNC16(a_base + (uint32_t)(j * S3PAD + c4) * 4,
                   absrc + (size_t)(jb0 + j) * 64 + 32 + c4);
    }
    CP_COMMIT();
    if (tid < 128) bo_s[tid] = b_out[tid];

    int wid = tid >> 5, lane = tid & 31;
    int g = lane >> 2, tg = lane & 3;
    int wm = wid & 1;          // j block of 32 (within 64-chunk)
    int wn = wid >> 1;         // p block of 32
    float norm = op_norm[b];
    int p0 = wn * 32 + 8 * tg; // this thread's 8 contiguous physical p

    for (int jc = 0; jc < 3; jc++) {
        int jbase = half * 192 + jc * 64;
        int buf = jc & 1;
        CP_WAIT0();
        __syncthreads();

        if (jc < 2) {
            uint32_t dstb = a_base + (uint32_t)((buf ^ 1) * 64 * S3PAD) * 4;
#pragma unroll
            for (int k = 0; k < 2; k++) {
                int seg = tid + k * 256;
                int j = seg >> 3, c4 = (seg & 7) * 4;
                CP_ASYNC16(dstb + (uint32_t)(j * S3PAD + c4) * 4,
                           absrc + (size_t)(jbase + 64 + j) * 64 + 32 + c4);
            }
            CP_COMMIT();
        } else {
            CP_COMMIT();
        }

        const uint32_t* ab = a_s[buf];
        float acc[2][4][4];
#pragma unroll
        for (int mt = 0; mt < 2; mt++)
#pragma unroll
            for (int nt = 0; nt < 4; nt++)
#pragma unroll
                for (int r = 0; r < 4; r++) acc[mt][nt][r] = 0.f;

#pragma unroll
        for (int ks = 0; ks < 4; ks++) {
            int kk = ks * 8 + 2 * tg;
            uint32_t af[2][4];
#pragma unroll
            for (int mt = 0; mt < 2; mt++) {
                int r0 = wm * 32 + mt * 16;
                uint2 lo = *(const uint2*)&ab[(r0 + g) * S3PAD + kk];     // k=tg, tg+4
                uint2 hi = *(const uint2*)&ab[(r0 + 8 + g) * S3PAD + kk];
                af[mt][0] = lo.x; af[mt][1] = hi.x;
                af[mt][2] = lo.y; af[mt][3] = hi.y;
            }
            uint32_t bf[4][2];
#pragma unroll
            for (int nt = 0; nt < 4; nt++) {
                uint2 bb = *(const uint2*)&t_s[(wn * 32 + nt * 8 + g) * S3PAD + kk];
                bf[nt][0] = bb.x; bf[nt][1] = bb.y;
            }
#pragma unroll
            for (int mt = 0; mt < 2; mt++)
#pragma unroll
                for (int nt = 0; nt < 4; nt++)
                    mma_tf32(acc[mt][nt], af[mt], bf[nt]);
        }

        // epilogue: thread owns rows {wm*32+mt*16+g, +8} x 8 contiguous p at p0
        size_t obase = ((size_t)row * NN + jbase) * DPAIR;
        float bz0 = bo_s[p0 + 0] * norm, bz1 = bo_s[p0 + 1] * norm;
        float bz2 = bo_s[p0 + 2] * norm, bz3 = bo_s[p0 + 3] * norm;
        float bz4 = bo_s[p0 + 4] * norm, bz5 = bo_s[p0 + 5] * norm;
        float bz6 = bo_s[p0 + 6] * norm, bz7 = bo_s[p0 + 7] * norm;
#pragma unroll
        for (int mt = 0; mt < 2; mt++) {
            int j0 = wm * 32 + mt * 16 + g;
            float* r0p = out + obase + (size_t)j0 * DPAIR + p0;
            float* r1p = out + obase + (size_t)(j0 + 8) * DPAIR + p0;
            float4 v;
            v.x = fmaf(acc[mt][0][0], norm, bz0); v.y = fmaf(acc[mt][0][1], norm, bz1);
            v.z = fmaf(acc[mt][1][0], norm, bz2); v.w = fmaf(acc[mt][1][1], norm, bz3);
            __stcs((float4*)r0p, v);
            v.x = fmaf(acc[mt][2][0], norm, bz4); v.y = fmaf(acc[mt][2][1], norm, bz5);
            v.z = fmaf(acc[mt][3][0], norm, bz6); v.w = fmaf(acc[mt][3][1], norm, bz7);
            __stcs((float4*)(r0p + 4), v);
            v.x = fmaf(acc[mt][0][2], norm, bz0); v.y = fmaf(acc[mt][0][3], norm, bz1);
            v.z = fmaf(acc[mt][1][2], norm, bz2); v.w = fmaf(acc[mt][1][3], norm, bz3);
            __stcs((float4*)r1p, v);
            v.x = fmaf(acc[mt][2][2], norm, bz4); v.y = fmaf(acc[mt][2][3], norm, bz5);
            v.z = fmaf(acc[mt][3][2], norm, bz6); v.w = fmaf(acc[mt][3][3], norm, bz7);
            __stcs((float4*)(r1p + 4), v);
        }
    }
}

// ---------------- launch ----------------
extern "C" void kernel_launch(void* const* d_in, const int* in_sizes, int n_in,
                              void* d_out, int out_size)
{
    const float* m       = (const float*)d_in[0];
    const float* op_mask = (const float*)d_in[1];
    const float* op_norm = (const float*)d_in[2];
    const float* W_in    = (const float*)d_in[3];
    const float* b_in    = (const float*)d_in[4];
    const float* W_out   = (const float*)d_in[5];
    const float* b_out   = (const float*)d_in[6];
    float* out = (float*)d_out;

    stage1a<<<dim3(96, 4), 256>>>(m, W_in);
    stage1b<<<192, 256>>>(b_in, op_mask);
    stage2_t<<<dim3(8, 24), 256>>>(W_out);
    stage3_mma<<<dim3(2, NN, BSZ), 256>>>(b_out, op_norm, out);
}